// round 4
// baseline (speedup 1.0000x reference)
#include <cuda_runtime.h>
#include <cstdint>

// out[b] = (X X^T) X == X (X^T X);  G = X^T X is 128x128 per batch.
// Tensor-core path: mma.sync.m16n8k8 tf32 with 3-term hi/lo compensation.
// R4: 512 threads / 16 warps per CTA (32x32 tile per warp) to double per-SMSP
// warp concurrency and lift tensor-pipe utilization (was 35.6% @ 8 warps).

#define NB     4
#define TT     4096
#define DD     128
#define SPLITS 32
#define CHUNK  128
#define P1     132   // pitch for 128-wide tiles; 132 % 32 == 4 -> conflict-free frag reads
#define PX     68    // pitch for 64-wide X half tiles; 68 % 32 == 4

__device__ float g_partial[NB * SPLITS * DD * DD];  // 8 MB
__device__ float g_G[NB * DD * DD];                 // 256 KB

__device__ __forceinline__ uint32_t f2tf32(float v) {
    uint32_t u;
    asm("cvt.rna.tf32.f32 %0, %1;" : "=r"(u) : "f"(v));
    return u;
}

__device__ __forceinline__ void mma_tf32(float* d, const uint32_t* a, const uint32_t* b) {
    asm volatile(
        "mma.sync.aligned.m16n8k8.row.col.f32.tf32.tf32.f32 "
        "{%0,%1,%2,%3}, {%4,%5,%6,%7}, {%8,%9}, {%0,%1,%2,%3};"
        : "+f"(d[0]), "+f"(d[1]), "+f"(d[2]), "+f"(d[3])
        : "r"(a[0]), "r"(a[1]), "r"(a[2]), "r"(a[3]), "r"(b[0]), "r"(b[1]));
}

// ---------------------------------------------------------------------------
// Kernel 1: P[b,s] = Xc^T * Xc   (tensor cores), 512 threads, 16 warps 4x4.
// smem: X^T hi/lo, layout [d][t] pitch 132.
// ---------------------------------------------------------------------------
__global__ void __launch_bounds__(512, 1)
syrk_kernel(const float* __restrict__ x)
{
    extern __shared__ float sm[];
    float* Hi = sm;               // [128][132]
    float* Lo = sm + DD * P1;     // [128][132]

    const int s = blockIdx.x, b = blockIdx.y;
    const int tid = threadIdx.x, lane = tid & 31, w = tid >> 5;

    const float4* xg = reinterpret_cast<const float4*>(
        x + ((size_t)b * TT + (size_t)s * CHUNK) * DD);

    // Transposed fill: warp covers 16 t-rows x 2 kq per iter; 16 warps split kq range.
    {
        const int t = (w & 7) * 16 + (lane >> 1);
        const int kb = (w >> 3) * 16;
#pragma unroll
        for (int j = 0; j < 8; j++) {
            const int kq = kb + (lane & 1) + 2 * j;
            float4 v = xg[t * 32 + kq];
            float vv[4] = {v.x, v.y, v.z, v.w};
#pragma unroll
            for (int i = 0; i < 4; i++) {
                float hi = __uint_as_float(f2tf32(vv[i]));
                float lo = __uint_as_float(f2tf32(vv[i] - hi));
                Hi[(4 * kq + i) * P1 + t] = hi;
                Lo[(4 * kq + i) * P1 + t] = lo;
            }
        }
    }
    __syncthreads();

    const int m0 = (w >> 2) * 32;
    const int n0 = (w & 3) * 32;
    const int gr = lane >> 2;
    const int gc = lane & 3;

    float acc[2][4][4];
#pragma unroll
    for (int mt = 0; mt < 2; mt++)
#pragma unroll
        for (int nt = 0; nt < 4; nt++)
#pragma unroll
            for (int q = 0; q < 4; q++) acc[mt][nt][q] = 0.0f;

    const uint32_t* HiU = reinterpret_cast<const uint32_t*>(Hi);
    const uint32_t* LoU = reinterpret_cast<const uint32_t*>(Lo);

#pragma unroll 1
    for (int k0 = 0; k0 < 128; k0 += 8) {
        uint32_t ah[2][4], al[2][4];
#pragma unroll
        for (int mt = 0; mt < 2; mt++) {
            const int r = (m0 + mt * 16 + gr) * P1 + k0 + gc;
            ah[mt][0] = HiU[r];              al[mt][0] = LoU[r];
            ah[mt][1] = HiU[r + 8 * P1];     al[mt][1] = LoU[r + 8 * P1];
            ah[mt][2] = HiU[r + 4];          al[mt][2] = LoU[r + 4];
            ah[mt][3] = HiU[r + 8 * P1 + 4]; al[mt][3] = LoU[r + 8 * P1 + 4];
        }
#pragma unroll
        for (int nt = 0; nt < 4; nt++) {
            const int rn = (n0 + nt * 8 + gr) * P1 + k0 + gc;
            uint32_t bh[2] = {HiU[rn], HiU[rn + 4]};
            uint32_t bl[2] = {LoU[rn], LoU[rn + 4]};
#pragma unroll
            for (int mt = 0; mt < 2; mt++) {
                mma_tf32(acc[mt][nt], ah[mt], bh);
                mma_tf32(acc[mt][nt], ah[mt], bl);
                mma_tf32(acc[mt][nt], al[mt], bh);
            }
        }
    }

    float* outp = g_partial + (size_t)(b * SPLITS + s) * DD * DD;
#pragma unroll
    for (int mt = 0; mt < 2; mt++)
#pragma unroll
        for (int nt = 0; nt < 4; nt++) {
            const int row = m0 + mt * 16 + gr;
            const int col = n0 + nt * 8 + 2 * gc;
            *reinterpret_cast<float2*>(outp + row * DD + col) =
                make_float2(acc[mt][nt][0], acc[mt][nt][1]);
            *reinterpret_cast<float2*>(outp + (row + 8) * DD + col) =
                make_float2(acc[mt][nt][2], acc[mt][nt][3]);
        }
}

// ---------------------------------------------------------------------------
// Kernel 2: G[b] = sum_s P[b,s]
// ---------------------------------------------------------------------------
__global__ void __launch_bounds__(256, 1)
reduce_kernel()
{
    const int idx = blockIdx.x * 256 + threadIdx.x;  // float4 index
    const int b = idx >> 12;
    const int e = idx & 4095;

    const float4* base = reinterpret_cast<const float4*>(g_partial)
                       + (size_t)b * SPLITS * 4096 + e;
    float4 acc = make_float4(0.f, 0.f, 0.f, 0.f);
#pragma unroll
    for (int s = 0; s < SPLITS; s++) {
        float4 v = base[(size_t)s * 4096];
        acc.x += v.x; acc.y += v.y; acc.z += v.z; acc.w += v.w;
    }
    reinterpret_cast<float4*>(g_G)[idx] = acc;
}

// ---------------------------------------------------------------------------
// Kernel 3: out_chunk = Xc * G[b]  (tensor cores), 512 threads, 16 warps 4x4.
// A = Xc row-major (k-halved staging); B-frags read Gs[n][k] (G symmetric).
// ---------------------------------------------------------------------------
__global__ void __launch_bounds__(512, 1)
gemm_kernel(const float* __restrict__ x, float* __restrict__ out)
{
    extern __shared__ float sm[];
    float* Ghi = sm;                    // [128][132]
    float* Glo = sm + DD * P1;          // [128][132]
    float* Xhi = sm + 2 * DD * P1;      // [128][68]
    float* Xlo = sm + 2 * DD * P1 + DD * PX;

    const int s = blockIdx.x, b = blockIdx.y;
    const int tid = threadIdx.x, lane = tid & 31, w = tid >> 5;

    const float4* xg = reinterpret_cast<const float4*>(
        x + ((size_t)b * TT + (size_t)s * CHUNK) * DD);
    const float4* gg = reinterpret_cast<const float4*>(g_G + (size_t)b * DD * DD);

    // Fill G hi/lo (row-major, pitch 132)
#pragma unroll
    for (int j = 0; j < 8; j++) {
        const int idx = tid + j * 512;
        const int n = idx >> 5, kq = idx & 31;
        float4 v = gg[idx];
        float4 h, l;
        h.x = __uint_as_float(f2tf32(v.x)); l.x = __uint_as_float(f2tf32(v.x - h.x));
        h.y = __uint_as_float(f2tf32(v.y)); l.y = __uint_as_float(f2tf32(v.y - h.y));
        h.z = __uint_as_float(f2tf32(v.z)); l.z = __uint_as_float(f2tf32(v.z - h.z));
        h.w = __uint_as_float(f2tf32(v.w)); l.w = __uint_as_float(f2tf32(v.w - h.w));
        *reinterpret_cast<float4*>(Ghi + n * P1 + 4 * kq) = h;
        *reinterpret_cast<float4*>(Glo + n * P1 + 4 * kq) = l;
    }
    // Fill X half 0 (k in [0,64))
#pragma unroll
    for (int j = 0; j < 4; j++) {
        const int idx = tid + j * 512;
        const int t = idx >> 4, kq = idx & 15;
        float4 v = xg[t * 32 + kq];
        float4 h, l;
        h.x = __uint_as_float(f2tf32(v.x)); l.x = __uint_as_float(f2tf32(v.x - h.x));
        h.y = __uint_as_float(f2tf32(v.y)); l.y = __uint_as_float(f2tf32(v.y - h.y));
        h.z = __uint_as_float(f2tf32(v.z)); l.z = __uint_as_float(f2tf32(v.z - h.z));
        h.w = __uint_as_float(f2tf32(v.w)); l.w = __uint_as_float(f2tf32(v.w - h.w));
        *reinterpret_cast<float4*>(Xhi + t * PX + 4 * kq) = h;
        *reinterpret_cast<float4*>(Xlo + t * PX + 4 * kq) = l;
    }
    __syncthreads();

    const int m0 = (w >> 2) * 32;
    const int n0 = (w & 3) * 32;
    const int gr = lane >> 2;
    const int gc = lane & 3;

    float acc[2][4][4];
#pragma unroll
    for (int mt = 0; mt < 2; mt++)
#pragma unroll
        for (int nt = 0; nt < 4; nt++)
#pragma unroll
            for (int q = 0; q < 4; q++) acc[mt][nt][q] = 0.0f;

    const uint32_t* GhU = reinterpret_cast<const uint32_t*>(Ghi);
    const uint32_t* GlU = reinterpret_cast<const uint32_t*>(Glo);
    const uint32_t* XhU = reinterpret_cast<const uint32_t*>(Xhi);
    const uint32_t* XlU = reinterpret_cast<const uint32_t*>(Xlo);

#pragma unroll 1
    for (int h = 0; h < 2; h++) {
#pragma unroll 1
        for (int k0 = 0; k0 < 64; k0 += 8) {
            uint32_t ah[2][4], al[2][4];
#pragma unroll
            for (int mt = 0; mt < 2; mt++) {
                const int r = (m0 + mt * 16 + gr) * PX + k0 + gc;
                ah[mt][0] = XhU[r];              al[mt][0] = XlU[r];
                ah[mt][1] = XhU[r + 8 * PX];     al[mt][1] = XlU[r + 8 * PX];
                ah[mt][2] = XhU[r + 4];          al[mt][2] = XlU[r + 4];
                ah[mt][3] = XhU[r + 8 * PX + 4]; al[mt][3] = XlU[r + 8 * PX + 4];
            }
            const int kg = h * 64 + k0;
#pragma unroll
            for (int nt = 0; nt < 4; nt++) {
                const int rn = (n0 + nt * 8 + gr) * P1 + kg + gc;
                uint32_t bh[2] = {GhU[rn], GhU[rn + 4]};
                uint32_t bl[2] = {GlU[rn], GlU[rn + 4]};
#pragma unroll
                for (int mt = 0; mt < 2; mt++) {
                    mma_tf32(acc[mt][nt], ah[mt], bh);
                    mma_tf32(acc[mt][nt], ah[mt], bl);
                    mma_tf32(acc[mt][nt], al[mt], bh);
                }
            }
        }
        if (h == 0) {
            __syncthreads();
            // Fill X half 1 (k in [64,128))
#pragma unroll
            for (int j = 0; j < 4; j++) {
                const int idx = tid + j * 512;
                const int t = idx >> 4, kq = idx & 15;
                float4 v = xg[t * 32 + 16 + kq];
                float4 hh, ll;
                hh.x = __uint_as_float(f2tf32(v.x)); ll.x = __uint_as_float(f2tf32(v.x - hh.x));
                hh.y = __uint_as_float(f2tf32(v.y)); ll.y = __uint_as_float(f2tf32(v.y - hh.y));
                hh.z = __uint_as_float(f2tf32(v.z)); ll.z = __uint_as_float(f2tf32(v.z - hh.z));
                hh.w = __uint_as_float(f2tf32(v.w)); ll.w = __uint_as_float(f2tf32(v.w - hh.w));
                *reinterpret_cast<float4*>(Xhi + t * PX + 4 * kq) = hh;
                *reinterpret_cast<float4*>(Xlo + t * PX + 4 * kq) = ll;
            }
            __syncthreads();
        }
    }

    float* ob = out + ((size_t)b * TT + (size_t)s * CHUNK) * DD;
#pragma unroll
    for (int mt = 0; mt < 2; mt++)
#pragma unroll
        for (int nt = 0; nt < 4; nt++) {
            const int row = m0 + mt * 16 + gr;
            const int col = n0 + nt * 8 + 2 * gc;
            *reinterpret_cast<float2*>(ob + row * DD + col) =
                make_float2(acc[mt][nt][0], acc[mt][nt][1]);
            *reinterpret_cast<float2*>(ob + (row + 8) * DD + col) =
                make_float2(acc[mt][nt][2], acc[mt][nt][3]);
        }
}

// ---------------------------------------------------------------------------

extern "C" void kernel_launch(void* const* d_in, const int* in_sizes, int n_in,
                              void* d_out, int out_size)
{
    (void)in_sizes; (void)n_in; (void)out_size;
    const float* x = (const float*)d_in[0];
    float* out = (float*)d_out;

    const int smem1 = 2 * DD * P1 * 4;                    // 135168 B
    const int smem3 = 2 * DD * P1 * 4 + 2 * DD * PX * 4;  // 204800 B

    cudaFuncSetAttribute(syrk_kernel, cudaFuncAttributeMaxDynamicSharedMemorySize, smem1);
    cudaFuncSetAttribute(gemm_kernel, cudaFuncAttributeMaxDynamicSharedMemorySize, smem3);

    syrk_kernel<<<dim3(SPLITS, NB), 512, smem1>>>(x);
    reduce_kernel<<<64, 256>>>();
    gemm_kernel<<<dim3(SPLITS, NB), 512, smem3>>>(x, out);
}

// round 5
// speedup vs baseline: 1.2764x; 1.2764x over previous
#include <cuda_runtime.h>
#include <cuda_bf16.h>
#include <cstdint>

// out[b] = (X X^T) X == X (X^T X);  G = X^T X is 128x128 per batch.
// R5: bf16 3-term compensated split (hh + hl + lh, residual ~2^-18) with
// mma.sync.m16n8k16 (2x MACs/instr vs tf32 m16n8k8) + ldmatrix.x4 operand loads.
// MMA instruction count halves -> halves time if MMA-issue-bound (R4 evidence).

#define NB     4
#define TT     4096
#define DD     128
#define SPLITS 32
#define CHUNK  128
#define PB     136   // bf16 pitch: 272B; 272 mod 128 == 16 -> ldmatrix conflict-free

__device__ float g_partial[NB * SPLITS * DD * DD];  // 8 MB
__device__ float g_G[NB * DD * DD];                 // 256 KB

__device__ __forceinline__ uint32_t smem_u32(const void* p) {
    uint32_t a;
    asm("{ .reg .u64 t; cvta.to.shared.u64 t, %1; cvt.u32.u64 %0, t; }" : "=r"(a) : "l"(p));
    return a;
}

__device__ __forceinline__ void ldm_x4(uint32_t* r, uint32_t addr) {
    asm volatile("ldmatrix.sync.aligned.m8n8.x4.shared.b16 {%0,%1,%2,%3}, [%4];"
                 : "=r"(r[0]), "=r"(r[1]), "=r"(r[2]), "=r"(r[3]) : "r"(addr));
}

__device__ __forceinline__ void mma_bf16(float* d, const uint32_t* a, uint32_t b0, uint32_t b1) {
    asm volatile(
        "mma.sync.aligned.m16n8k16.row.col.f32.bf16.bf16.f32 "
        "{%0,%1,%2,%3}, {%4,%5,%6,%7}, {%8,%9}, {%0,%1,%2,%3};"
        : "+f"(d[0]), "+f"(d[1]), "+f"(d[2]), "+f"(d[3])
        : "r"(a[0]), "r"(a[1]), "r"(a[2]), "r"(a[3]), "r"(b0), "r"(b1));
}

__device__ __forceinline__ void split_bf16(float v, __nv_bfloat16& h, __nv_bfloat16& l) {
    h = __float2bfloat16_rn(v);
    l = __float2bfloat16_rn(v - __bfloat162float(h));
}

// ---------------------------------------------------------------------------
// Kernel 1: P[b,s] = Xc^T * Xc.  A = B = X^T tile in smem, layout [d][t], bf16
// hi/lo planes, pitch 136. 512 threads, 16 warps (4x4 grid of 32x32 tiles).
// ---------------------------------------------------------------------------
__global__ void __launch_bounds__(512, 1)
syrk_kernel(const float* __restrict__ x)
{
    extern __shared__ char smc[];
    __nv_bfloat16* Hi = reinterpret_cast<__nv_bfloat16*>(smc);
    __nv_bfloat16* Lo = Hi + DD * PB;

    const int s = blockIdx.x, b = blockIdx.y;
    const int tid = threadIdx.x, lane = tid & 31, w = tid >> 5;

    const float4* xg = reinterpret_cast<const float4*>(
        x + ((size_t)b * TT + (size_t)s * CHUNK) * DD);

    // Transposed fill: X[t][d] -> Hi/Lo[d][t]
    {
        const int t = (w & 7) * 16 + (lane >> 1);
        const int kb = (w >> 3) * 16;
#pragma unroll
        for (int j = 0; j < 8; j++) {
            const int kq = kb + (lane & 1) + 2 * j;
            float4 v = xg[t * 32 + kq];
            float vv[4] = {v.x, v.y, v.z, v.w};
#pragma unroll
            for (int i = 0; i < 4; i++) {
                __nv_bfloat16 h, l;
                split_bf16(vv[i], h, l);
                Hi[(4 * kq + i) * PB + t] = h;
                Lo[(4 * kq + i) * PB + t] = l;
            }
        }
    }
    __syncthreads();

    const int m0 = (w >> 2) * 32;
    const int n0 = (w & 3) * 32;
    const int gr = lane >> 2;
    const int gc = lane & 3;

    const uint32_t hiB = smem_u32(Hi);
    const uint32_t loB = smem_u32(Lo);
    // ldmatrix lane row/col offsets (x4: lanes 0-15 -> k lo, 16-31 -> k hi)
    const uint32_t lrow = (uint32_t)(lane & 15);
    const uint32_t lkof = (uint32_t)((lane >> 4) << 3);

    float acc[2][4][4];
#pragma unroll
    for (int mt = 0; mt < 2; mt++)
#pragma unroll
        for (int nt = 0; nt < 4; nt++)
#pragma unroll
            for (int q = 0; q < 4; q++) acc[mt][nt][q] = 0.0f;

#pragma unroll 1
    for (int k0 = 0; k0 < 128; k0 += 16) {
        uint32_t ah[2][4], al[2][4], bh[2][4], bl[2][4];
#pragma unroll
        for (int mt = 0; mt < 2; mt++) {
            uint32_t off = (((uint32_t)(m0 + mt * 16) + lrow) * PB + (uint32_t)k0 + lkof) * 2;
            ldm_x4(ah[mt], hiB + off);
            ldm_x4(al[mt], loB + off);
        }
#pragma unroll
        for (int ng = 0; ng < 2; ng++) {
            uint32_t off = (((uint32_t)(n0 + ng * 16) + lrow) * PB + (uint32_t)k0 + lkof) * 2;
            ldm_x4(bh[ng], hiB + off);
            ldm_x4(bl[ng], loB + off);
        }
#pragma unroll
        for (int ng = 0; ng < 2; ng++)
#pragma unroll
            for (int sub = 0; sub < 2; sub++) {
                const int nt = ng * 2 + sub;
#pragma unroll
                for (int mt = 0; mt < 2; mt++) {
                    mma_bf16(acc[mt][nt], ah[mt], bh[ng][sub], bh[ng][sub + 2]);
                    mma_bf16(acc[mt][nt], ah[mt], bl[ng][sub], bl[ng][sub + 2]);
                    mma_bf16(acc[mt][nt], al[mt], bh[ng][sub], bh[ng][sub + 2]);
                }
            }
    }

    float* outp = g_partial + (size_t)(b * SPLITS + s) * DD * DD;
#pragma unroll
    for (int mt = 0; mt < 2; mt++)
#pragma unroll
        for (int nt = 0; nt < 4; nt++) {
            const int row = m0 + mt * 16 + gr;
            const int col = n0 + nt * 8 + 2 * gc;
            *reinterpret_cast<float2*>(outp + row * DD + col) =
                make_float2(acc[mt][nt][0], acc[mt][nt][1]);
            *reinterpret_cast<float2*>(outp + (row + 8) * DD + col) =
                make_float2(acc[mt][nt][2], acc[mt][nt][3]);
        }
}

// ---------------------------------------------------------------------------
// Kernel 2: G[b] = sum_s P[b,s]
// ---------------------------------------------------------------------------
__global__ void __launch_bounds__(256, 1)
reduce_kernel()
{
    const int idx = blockIdx.x * 256 + threadIdx.x;
    const int b = idx >> 12;
    const int e = idx & 4095;

    const float4* base = reinterpret_cast<const float4*>(g_partial)
                       + (size_t)b * SPLITS * 4096 + e;
    float4 acc = make_float4(0.f, 0.f, 0.f, 0.f);
#pragma unroll
    for (int s = 0; s < SPLITS; s++) {
        float4 v = base[(size_t)s * 4096];
        acc.x += v.x; acc.y += v.y; acc.z += v.z; acc.w += v.w;
    }
    reinterpret_cast<float4*>(g_G)[idx] = acc;
}

// ---------------------------------------------------------------------------
// Kernel 3: out_chunk = Xc * G[b].  A = Xc row-major [t][d] (m=t,k=d);
// B = G [n][k] row-major (G symmetric). Both bf16 hi/lo, pitch 136.
// ---------------------------------------------------------------------------
__global__ void __launch_bounds__(512, 1)
gemm_kernel(const float* __restrict__ x, float* __restrict__ out)
{
    extern __shared__ char smc[];
    __nv_bfloat16* Ghi = reinterpret_cast<__nv_bfloat16*>(smc);
    __nv_bfloat16* Glo = Ghi + DD * PB;
    __nv_bfloat16* Xhi = Glo + DD * PB;
    __nv_bfloat16* Xlo = Xhi + DD * PB;

    const int s = blockIdx.x, b = blockIdx.y;
    const int tid = threadIdx.x, lane = tid & 31, w = tid >> 5;

    const float4* xg = reinterpret_cast<const float4*>(
        x + ((size_t)b * TT + (size_t)s * CHUNK) * DD);
    const float4* gg = reinterpret_cast<const float4*>(g_G + (size_t)b * DD * DD);

    // Row-major fills (coalesced reads; bf162-pair stores)
#pragma unroll
    for (int j = 0; j < 8; j++) {
        const int idx = tid + j * 512;
        const int r = idx >> 5, kq = idx & 31;
        {
            float4 v = gg[idx];
            __nv_bfloat16 hx, lx, hy, ly, hz, lz, hw, lw;
            split_bf16(v.x, hx, lx); split_bf16(v.y, hy, ly);
            split_bf16(v.z, hz, lz); split_bf16(v.w, hw, lw);
            __nv_bfloat162* dh = reinterpret_cast<__nv_bfloat162*>(Ghi + r * PB + 4 * kq);
            __nv_bfloat162* dl = reinterpret_cast<__nv_bfloat162*>(Glo + r * PB + 4 * kq);
            dh[0] = __nv_bfloat162(hx, hy); dh[1] = __nv_bfloat162(hz, hw);
            dl[0] = __nv_bfloat162(lx, ly); dl[1] = __nv_bfloat162(lz, lw);
        }
        {
            float4 v = xg[idx];
            __nv_bfloat16 hx, lx, hy, ly, hz, lz, hw, lw;
            split_bf16(v.x, hx, lx); split_bf16(v.y, hy, ly);
            split_bf16(v.z, hz, lz); split_bf16(v.w, hw, lw);
            __nv_bfloat162* dh = reinterpret_cast<__nv_bfloat162*>(Xhi + r * PB + 4 * kq);
            __nv_bfloat162* dl = reinterpret_cast<__nv_bfloat162*>(Xlo + r * PB + 4 * kq);
            dh[0] = __nv_bfloat162(hx, hy); dh[1] = __nv_bfloat162(hz, hw);
            dl[0] = __nv_bfloat162(lx, ly); dl[1] = __nv_bfloat162(lz, lw);
        }
    }
    __syncthreads();

    const int m0 = (w >> 2) * 32;
    const int n0 = (w & 3) * 32;
    const int gr = lane >> 2;
    const int gc = lane & 3;

    const uint32_t xhB = smem_u32(Xhi);
    const uint32_t xlB = smem_u32(Xlo);
    const uint32_t ghB = smem_u32(Ghi);
    const uint32_t glB = smem_u32(Glo);
    const uint32_t lrow = (uint32_t)(lane & 15);
    const uint32_t lkof = (uint32_t)((lane >> 4) << 3);

    float acc[2][4][4];
#pragma unroll
    for (int mt = 0; mt < 2; mt++)
#pragma unroll
        for (int nt = 0; nt < 4; nt++)
#pragma unroll
            for (int q = 0; q < 4; q++) acc[mt][nt][q] = 0.0f;

#pragma unroll 1
    for (int k0 = 0; k0 < 128; k0 += 16) {
        uint32_t ah[2][4], al[2][4], bh[2][4], bl[2][4];
#pragma unroll
        for (int mt = 0; mt < 2; mt++) {
            uint32_t off = (((uint32_t)(m0 + mt * 16) + lrow) * PB + (uint32_t)k0 + lkof) * 2;
            ldm_x4(ah[mt], xhB + off);
            ldm_x4(al[mt], xlB + off);
        }
#pragma unroll
        for (int ng = 0; ng < 2; ng++) {
            uint32_t off = (((uint32_t)(n0 + ng * 16) + lrow) * PB + (uint32_t)k0 + lkof) * 2;
            ldm_x4(bh[ng], ghB + off);
            ldm_x4(bl[ng], glB + off);
        }
#pragma unroll
        for (int ng = 0; ng < 2; ng++)
#pragma unroll
            for (int sub = 0; sub < 2; sub++) {
                const int nt = ng * 2 + sub;
#pragma unroll
                for (int mt = 0; mt < 2; mt++) {
                    mma_bf16(acc[mt][nt], ah[mt], bh[ng][sub], bh[ng][sub + 2]);
                    mma_bf16(acc[mt][nt], ah[mt], bl[ng][sub], bl[ng][sub + 2]);
                    mma_bf16(acc[mt][nt], al[mt], bh[ng][sub], bh[ng][sub + 2]);
                }
            }
    }

    float* ob = out + ((size_t)b * TT + (size_t)s * CHUNK) * DD;
#pragma unroll
    for (int mt = 0; mt < 2; mt++)
#pragma unroll
        for (int nt = 0; nt < 4; nt++) {
            const int row = m0 + mt * 16 + gr;
            const int col = n0 + nt * 8 + 2 * gc;
            *reinterpret_cast<float2*>(ob + row * DD + col) =
                make_float2(acc[mt][nt][0], acc[mt][nt][1]);
            *reinterpret_cast<float2*>(ob + (row + 8) * DD + col) =
                make_float2(acc[mt][nt][2], acc[mt][nt][3]);
        }
}

// ---------------------------------------------------------------------------

extern "C" void kernel_launch(void* const* d_in, const int* in_sizes, int n_in,
                              void* d_out, int out_size)
{
    (void)in_sizes; (void)n_in; (void)out_size;
    const float* x = (const float*)d_in[0];
    float* out = (float*)d_out;

    const int smem1 = 2 * DD * PB * 2;  // 69632 B
    const int smem3 = 4 * DD * PB * 2;  // 139264 B

    cudaFuncSetAttribute(syrk_kernel, cudaFuncAttributeMaxDynamicSharedMemorySize, smem1);
    cudaFuncSetAttribute(gemm_kernel, cudaFuncAttributeMaxDynamicSharedMemorySize, smem3);

    syrk_kernel<<<dim3(SPLITS, NB), 512, smem1>>>(x);
    reduce_kernel<<<64, 256>>>();
    gemm_kernel<<<dim3(SPLITS, NB), 512, smem3>>>(x, out);
}

// round 6
// speedup vs baseline: 1.2782x; 1.0014x over previous
#include <cuda_runtime.h>
#include <cuda_bf16.h>
#include <cstdint>

// out[b] = (X X^T) X == X (X^T X);  G = X^T X is 128x128 per batch.
// R6: dual-accumulator split (accP = hh; accQ = hl + lh) halves the dependent
// HMMA chain length, and the k-loop is fully unrolled so ptxas can pipeline
// next-iter ldmatrix into the current MMA block. (R5 showed stall-bound:
// tensor 22%, issue 25%.)

#define NB     4
#define TT     4096
#define DD     128
#define SPLITS 32
#define CHUNK  128
#define PB     136   // bf16 pitch: 272B; 272 mod 128 == 16 -> ldmatrix conflict-free

__device__ float g_partial[NB * SPLITS * DD * DD];  // 8 MB
__device__ float g_G[NB * DD * DD];                 // 256 KB

__device__ __forceinline__ uint32_t smem_u32(const void* p) {
    uint32_t a;
    asm("{ .reg .u64 t; cvta.to.shared.u64 t, %1; cvt.u32.u64 %0, t; }" : "=r"(a) : "l"(p));
    return a;
}

__device__ __forceinline__ void ldm_x4(uint32_t* r, uint32_t addr) {
    asm volatile("ldmatrix.sync.aligned.m8n8.x4.shared.b16 {%0,%1,%2,%3}, [%4];"
                 : "=r"(r[0]), "=r"(r[1]), "=r"(r[2]), "=r"(r[3]) : "r"(addr));
}

__device__ __forceinline__ void mma_bf16(float* d, const uint32_t* a, uint32_t b0, uint32_t b1) {
    asm volatile(
        "mma.sync.aligned.m16n8k16.row.col.f32.bf16.bf16.f32 "
        "{%0,%1,%2,%3}, {%4,%5,%6,%7}, {%8,%9}, {%0,%1,%2,%3};"
        : "+f"(d[0]), "+f"(d[1]), "+f"(d[2]), "+f"(d[3])
        : "r"(a[0]), "r"(a[1]), "r"(a[2]), "r"(a[3]), "r"(b0), "r"(b1));
}

__device__ __forceinline__ void split_bf16(float v, __nv_bfloat16& h, __nv_bfloat16& l) {
    h = __float2bfloat16_rn(v);
    l = __float2bfloat16_rn(v - __bfloat162float(h));
}

// ---------------------------------------------------------------------------
// Kernel 1: P[b,s] = Xc^T * Xc.  smem X^T hi/lo bf16, [d][t] pitch 136.
// 512 threads, 16 warps (4x4 grid of 32x32 output tiles).
// ---------------------------------------------------------------------------
__global__ void __launch_bounds__(512, 1)
syrk_kernel(const float* __restrict__ x)
{
    extern __shared__ char smc[];
    __nv_bfloat16* Hi = reinterpret_cast<__nv_bfloat16*>(smc);
    __nv_bfloat16* Lo = Hi + DD * PB;

    const int s = blockIdx.x, b = blockIdx.y;
    const int tid = threadIdx.x, lane = tid & 31, w = tid >> 5;

    const float4* xg = reinterpret_cast<const float4*>(
        x + ((size_t)b * TT + (size_t)s * CHUNK) * DD);

    // Transposed fill: X[t][d] -> Hi/Lo[d][t]
    {
        const int t = (w & 7) * 16 + (lane >> 1);
        const int kb = (w >> 3) * 16;
#pragma unroll
        for (int j = 0; j < 8; j++) {
            const int kq = kb + (lane & 1) + 2 * j;
            float4 v = xg[t * 32 + kq];
            float vv[4] = {v.x, v.y, v.z, v.w};
#pragma unroll
            for (int i = 0; i < 4; i++) {
                __nv_bfloat16 h, l;
                split_bf16(vv[i], h, l);
                Hi[(4 * kq + i) * PB + t] = h;
                Lo[(4 * kq + i) * PB + t] = l;
            }
        }
    }
    __syncthreads();

    const int m0 = (w >> 2) * 32;
    const int n0 = (w & 3) * 32;
    const int gr = lane >> 2;
    const int gc = lane & 3;

    const uint32_t hiB = smem_u32(Hi);
    const uint32_t loB = smem_u32(Lo);
    const uint32_t lrow = (uint32_t)(lane & 15);
    const uint32_t lkof = (uint32_t)((lane >> 4) << 3);

    float accP[2][4][4], accQ[2][4][4];
#pragma unroll
    for (int mt = 0; mt < 2; mt++)
#pragma unroll
        for (int nt = 0; nt < 4; nt++)
#pragma unroll
            for (int q = 0; q < 4; q++) { accP[mt][nt][q] = 0.0f; accQ[mt][nt][q] = 0.0f; }

#pragma unroll
    for (int k0 = 0; k0 < 128; k0 += 16) {
        uint32_t ah[2][4], al[2][4], bh[2][4], bl[2][4];
#pragma unroll
        for (int mt = 0; mt < 2; mt++) {
            uint32_t off = (((uint32_t)(m0 + mt * 16) + lrow) * PB + (uint32_t)k0 + lkof) * 2;
            ldm_x4(ah[mt], hiB + off);
            ldm_x4(al[mt], loB + off);
        }
#pragma unroll
        for (int ng = 0; ng < 2; ng++) {
            uint32_t off = (((uint32_t)(n0 + ng * 16) + lrow) * PB + (uint32_t)k0 + lkof) * 2;
            ldm_x4(bh[ng], hiB + off);
            ldm_x4(bl[ng], loB + off);
        }
#pragma unroll
        for (int ng = 0; ng < 2; ng++)
#pragma unroll
            for (int sub = 0; sub < 2; sub++) {
                const int nt = ng * 2 + sub;
#pragma unroll
                for (int mt = 0; mt < 2; mt++) {
                    mma_bf16(accP[mt][nt], ah[mt], bh[ng][sub], bh[ng][sub + 2]);
                    mma_bf16(accQ[mt][nt], ah[mt], bl[ng][sub], bl[ng][sub + 2]);
                    mma_bf16(accQ[mt][nt], al[mt], bh[ng][sub], bh[ng][sub + 2]);
                }
            }
    }

    float* outp = g_partial + (size_t)(b * SPLITS + s) * DD * DD;
#pragma unroll
    for (int mt = 0; mt < 2; mt++)
#pragma unroll
        for (int nt = 0; nt < 4; nt++) {
            const int row = m0 + mt * 16 + gr;
            const int col = n0 + nt * 8 + 2 * gc;
            *reinterpret_cast<float2*>(outp + row * DD + col) =
                make_float2(accP[mt][nt][0] + accQ[mt][nt][0],
                            accP[mt][nt][1] + accQ[mt][nt][1]);
            *reinterpret_cast<float2*>(outp + (row + 8) * DD + col) =
                make_float2(accP[mt][nt][2] + accQ[mt][nt][2],
                            accP[mt][nt][3] + accQ[mt][nt][3]);
        }
}

// ---------------------------------------------------------------------------
// Kernel 2: G[b] = sum_s P[b,s]
// ---------------------------------------------------------------------------
__global__ void __launch_bounds__(128, 1)
reduce_kernel()
{
    const int idx = blockIdx.x * 128 + threadIdx.x;  // float4 index, 16384 total
    const int b = idx >> 12;
    const int e = idx & 4095;

    const float4* base = reinterpret_cast<const float4*>(g_partial)
                       + (size_t)b * SPLITS * 4096 + e;
    float4 acc = make_float4(0.f, 0.f, 0.f, 0.f);
#pragma unroll
    for (int s = 0; s < SPLITS; s++) {
        float4 v = base[(size_t)s * 4096];
        acc.x += v.x; acc.y += v.y; acc.z += v.z; acc.w += v.w;
    }
    reinterpret_cast<float4*>(g_G)[idx] = acc;
}

// ---------------------------------------------------------------------------
// Kernel 3: out_chunk = Xc * G[b].  A = Xc row-major; B = G row-major (symmetric).
// ---------------------------------------------------------------------------
__global__ void __launch_bounds__(512, 1)
gemm_kernel(const float* __restrict__ x, float* __restrict__ out)
{
    extern __shared__ char smc[];
    __nv_bfloat16* Ghi = reinterpret_cast<__nv_bfloat16*>(smc);
    __nv_bfloat16* Glo = Ghi + DD * PB;
    __nv_bfloat16* Xhi = Glo + DD * PB;
    __nv_bfloat16* Xlo = Xhi + DD * PB;

    const int s = blockIdx.x, b = blockIdx.y;
    const int tid = threadIdx.x, lane = tid & 31, w = tid >> 5;

    const float4* xg = reinterpret_cast<const float4*>(
        x + ((size_t)b * TT + (size_t)s * CHUNK) * DD);
    const float4* gg = reinterpret_cast<const float4*>(g_G + (size_t)b * DD * DD);

#pragma unroll
    for (int j = 0; j < 8; j++) {
        const int idx = tid + j * 512;
        const int r = idx >> 5, kq = idx & 31;
        {
            float4 v = gg[idx];
            __nv_bfloat16 hx, lx, hy, ly, hz, lz, hw, lw;
            split_bf16(v.x, hx, lx); split_bf16(v.y, hy, ly);
            split_bf16(v.z, hz, lz); split_bf16(v.w, hw, lw);
            __nv_bfloat162* dh = reinterpret_cast<__nv_bfloat162*>(Ghi + r * PB + 4 * kq);
            __nv_bfloat162* dl = reinterpret_cast<__nv_bfloat162*>(Glo + r * PB + 4 * kq);
            dh[0] = __nv_bfloat162(hx, hy); dh[1] = __nv_bfloat162(hz, hw);
            dl[0] = __nv_bfloat162(lx, ly); dl[1] = __nv_bfloat162(lz, lw);
        }
        {
            float4 v = xg[idx];
            __nv_bfloat16 hx, lx, hy, ly, hz, lz, hw, lw;
            split_bf16(v.x, hx, lx); split_bf16(v.y, hy, ly);
            split_bf16(v.z, hz, lz); split_bf16(v.w, hw, lw);
            __nv_bfloat162* dh = reinterpret_cast<__nv_bfloat162*>(Xhi + r * PB + 4 * kq);
            __nv_bfloat162* dl = reinterpret_cast<__nv_bfloat162*>(Xlo + r * PB + 4 * kq);
            dh[0] = __nv_bfloat162(hx, hy); dh[1] = __nv_bfloat162(hz, hw);
            dl[0] = __nv_bfloat162(lx, ly); dl[1] = __nv_bfloat162(lz, lw);
        }
    }
    __syncthreads();

    const int m0 = (w >> 2) * 32;
    const int n0 = (w & 3) * 32;
    const int gr = lane >> 2;
    const int gc = lane & 3;

    const uint32_t xhB = smem_u32(Xhi);
    const uint32_t xlB = smem_u32(Xlo);
    const uint32_t ghB = smem_u32(Ghi);
    const uint32_t glB = smem_u32(Glo);
    const uint32_t lrow = (uint32_t)(lane & 15);
    const uint32_t lkof = (uint32_t)((lane >> 4) << 3);

    float accP[2][4][4], accQ[2][4][4];
#pragma unroll
    for (int mt = 0; mt < 2; mt++)
#pragma unroll
        for (int nt = 0; nt < 4; nt++)
#pragma unroll
            for (int q = 0; q < 4; q++) { accP[mt][nt][q] = 0.0f; accQ[mt][nt][q] = 0.0f; }

#pragma unroll
    for (int k0 = 0; k0 < 128; k0 += 16) {
        uint32_t ah[2][4], al[2][4], bh[2][4], bl[2][4];
#pragma unroll
        for (int mt = 0; mt < 2; mt++) {
            uint32_t off = (((uint32_t)(m0 + mt * 16) + lrow) * PB + (uint32_t)k0 + lkof) * 2;
            ldm_x4(ah[mt], xhB + off);
            ldm_x4(al[mt], xlB + off);
        }
#pragma unroll
        for (int ng = 0; ng < 2; ng++) {
            uint32_t off = (((uint32_t)(n0 + ng * 16) + lrow) * PB + (uint32_t)k0 + lkof) * 2;
            ldm_x4(bh[ng], ghB + off);
            ldm_x4(bl[ng], glB + off);
        }
#pragma unroll
        for (int ng = 0; ng < 2; ng++)
#pragma unroll
            for (int sub = 0; sub < 2; sub++) {
                const int nt = ng * 2 + sub;
#pragma unroll
                for (int mt = 0; mt < 2; mt++) {
                    mma_bf16(accP[mt][nt], ah[mt], bh[ng][sub], bh[ng][sub + 2]);
                    mma_bf16(accQ[mt][nt], ah[mt], bl[ng][sub], bl[ng][sub + 2]);
                    mma_bf16(accQ[mt][nt], al[mt], bh[ng][sub], bh[ng][sub + 2]);
                }
            }
    }

    float* ob = out + ((size_t)b * TT + (size_t)s * CHUNK) * DD;
#pragma unroll
    for (int mt = 0; mt < 2; mt++)
#pragma unroll
        for (int nt = 0; nt < 4; nt++) {
            const int row = m0 + mt * 16 + gr;
            const int col = n0 + nt * 8 + 2 * gc;
            *reinterpret_cast<float2*>(ob + row * DD + col) =
                make_float2(accP[mt][nt][0] + accQ[mt][nt][0],
                            accP[mt][nt][1] + accQ[mt][nt][1]);
            *reinterpret_cast<float2*>(ob + (row + 8) * DD + col) =
                make_float2(accP[mt][nt][2] + accQ[mt][nt][2],
                            accP[mt][nt][3] + accQ[mt][nt][3]);
        }
}

// ---------------------------------------------------------------------------

extern "C" void kernel_launch(void* const* d_in, const int* in_sizes, int n_in,
                              void* d_out, int out_size)
{
    (void)in_sizes; (void)n_in; (void)out_size;
    const float* x = (const float*)d_in[0];
    float* out = (float*)d_out;

    const int smem1 = 2 * DD * PB * 2;  // 69632 B
    const int smem3 = 4 * DD * PB * 2;  // 139264 B

    cudaFuncSetAttribute(syrk_kernel, cudaFuncAttributeMaxDynamicSharedMemorySize, smem1);
    cudaFuncSetAttribute(gemm_kernel, cudaFuncAttributeMaxDynamicSharedMemorySize, smem3);

    syrk_kernel<<<dim3(SPLITS, NB), 512, smem1>>>(x);
    reduce_kernel<<<128, 128>>>();
    gemm_kernel<<<dim3(SPLITS, NB), 512, smem3>>>(x, out);
}